// round 4
// baseline (speedup 1.0000x reference)
#include <cuda_runtime.h>
#include <cuda_fp16.h>
#include <cstdint>

#define N_NODES 100000
#define N_EDGES 1600000
#define E_TOT   (N_EDGES + N_NODES)   // self loops appended
#define N_GRAPHS 1024
#define EPS_BN 1e-5f
#define SCAN_B 98                      // ceil(N_NODES / 1024)
#define FULLM 0xffffffffu

// ----------------------------- scratch (device globals) -----------------------------
__device__ int    g_is64;
__device__ int    g_src[E_TOT];
__device__ int    g_dst[E_TOT];
__device__ int    g_batch[N_NODES];
__device__ int    g_deg[N_NODES];
__device__ int    g_off[N_NODES + 1];
__device__ int    g_cur[N_NODES];
__device__ int    g_csr[E_TOT];
__device__ int    g_bsum[SCAN_B];
__device__ __half g_hlinh[N_NODES * 128];  // post-GEMM features, fp16 (attn gather input)
__device__ float  g_feat[N_NODES * 128];   // attn output (raw, pre-BN) / GEMM input
__device__ float  g_als[N_NODES * 4];
__device__ float  g_ald[N_NODES * 4];
__device__ float  g_bnsum[256];            // [0:128) sum, [128:256) sumsq
__device__ float  g_pool[N_GRAPHS * 128];  // mean (0..63) || max (64..127)

// ----------------------------- utility -----------------------------
__device__ __forceinline__ float eluf(float v) { return v > 0.f ? v : expm1f(v); }
__device__ __forceinline__ float lrelu(float v) { return v > 0.f ? v : 0.2f * v; }

__device__ __forceinline__ unsigned long long pack2(float x, float y) {
    unsigned long long r;
    asm("mov.b64 %0, {%1, %2};" : "=l"(r) : "f"(x), "f"(y));
    return r;
}
__device__ __forceinline__ float2 unpack2(unsigned long long v) {
    float2 r;
    asm("mov.b64 {%0, %1}, %2;" : "=f"(r.x), "=f"(r.y) : "l"(v));
    return r;
}
#define FMA_F32X2(acc, a, b) \
    asm("fma.rn.f32x2 %0, %1, %2, %0;" : "+l"(acc) : "l"(a), "l"(b))

// ----------------------------- dtype detection -----------------------------
__global__ void detect_kernel(const void* ei) {
    __shared__ int any;
    if (threadIdx.x == 0) any = 0;
    __syncthreads();
    const int* p = (const int*)ei;
    int local = 0;
    for (int i = threadIdx.x; i < 2048; i += 256)
        if (p[2 * i + 1] != 0) local = 1;
    if (local) atomicOr(&any, 1);
    __syncthreads();
    if (threadIdx.x == 0) g_is64 = any ? 0 : 1;
}

__global__ void zero_deg_kernel() {
    int i = blockIdx.x * 256 + threadIdx.x;
    if (i < N_NODES) g_deg[i] = 0;
}

__global__ void convert_kernel(const void* ei, const void* batch) {
    int i = blockIdx.x * 256 + threadIdx.x;
    int is64 = g_is64;
    if (i < E_TOT) {
        int s, d;
        if (i < N_EDGES) {
            if (is64) {
                s = (int)((const long long*)ei)[i];
                d = (int)((const long long*)ei)[N_EDGES + i];
            } else {
                s = ((const int*)ei)[i];
                d = ((const int*)ei)[N_EDGES + i];
            }
        } else {
            s = d = i - N_EDGES;
        }
        g_src[i] = s;
        g_dst[i] = d;
        atomicAdd(&g_deg[d], 1);
    }
    if (i < N_NODES) {
        g_batch[i] = is64 ? (int)((const long long*)batch)[i] : ((const int*)batch)[i];
    }
}

// ----------------------------- hierarchical exclusive scan -----------------------------
__global__ void scan_partial_kernel() {
    __shared__ int sh[512];
    int t = threadIdx.x;
    int base = blockIdx.x * 1024;
    int i0 = base + t, i1 = base + 512 + t;
    int v = ((i0 < N_NODES) ? g_deg[i0] : 0) + ((i1 < N_NODES) ? g_deg[i1] : 0);
    sh[t] = v;
    __syncthreads();
    for (int o = 256; o; o >>= 1) {
        if (t < o) sh[t] += sh[t + o];
        __syncthreads();
    }
    if (t == 0) g_bsum[blockIdx.x] = sh[0];
}

__global__ void scan_mid_kernel() {
    __shared__ int sh[128];
    int t = threadIdx.x;
    int orig = (t < SCAN_B) ? g_bsum[t] : 0;
    sh[t] = orig;
    __syncthreads();
    for (int o = 1; o < 128; o <<= 1) {
        int v = (t >= o) ? sh[t - o] : 0;
        __syncthreads();
        sh[t] += v;
        __syncthreads();
    }
    if (t < SCAN_B) g_bsum[t] = sh[t] - orig;
    if (t == 0) g_off[N_NODES] = E_TOT;
}

__global__ void scan_final_kernel() {
    __shared__ int wsum[16];
    int t = threadIdx.x;
    int base = blockIdx.x * 1024;
    int i0 = base + 2 * t, i1 = i0 + 1;
    int d0 = (i0 < N_NODES) ? g_deg[i0] : 0;
    int d1 = (i1 < N_NODES) ? g_deg[i1] : 0;
    int tsum = d0 + d1;
    int lane = t & 31, wid = t >> 5;
    int v = tsum;
#pragma unroll
    for (int o = 1; o < 32; o <<= 1) {
        int u = __shfl_up_sync(FULLM, v, o);
        if (lane >= o) v += u;
    }
    if (lane == 31) wsum[wid] = v;
    __syncthreads();
    if (t < 16) {
        int w = wsum[t];
#pragma unroll
        for (int o = 1; o < 16; o <<= 1) {
            int u = __shfl_up_sync(0xffffu, w, o);
            if (t >= o) w += u;
        }
        wsum[t] = w;
    }
    __syncthreads();
    int excl = v - tsum + (wid ? wsum[wid - 1] : 0) + g_bsum[blockIdx.x];
    if (i0 < N_NODES) { g_off[i0] = excl;      g_cur[i0] = excl; }
    if (i1 < N_NODES) { g_off[i1] = excl + d0; g_cur[i1] = excl + d0; }
}

__global__ void fill_kernel() {
    int i = blockIdx.x * 256 + threadIdx.x;
    if (i < E_TOT) {
        int p = atomicAdd(&g_cur[g_dst[i]], 1);
        g_csr[p] = g_src[i];
    }
}

// ----------------------------- layer-1 GEMM (5 -> 128) + als epilogue -----------------------
__global__ void gemm1_kernel(const float* __restrict__ x, const float* __restrict__ W1,
                             const float* __restrict__ aS, const float* __restrict__ aD) {
    int node = blockIdx.x * 8 + (threadIdx.x >> 5);
    int lane = threadIdx.x & 31;
    if (node >= N_NODES) return;
    float acc[4] = {0.f, 0.f, 0.f, 0.f};
    const float* xr = x + node * 5;
#pragma unroll
    for (int k = 0; k < 5; k++) {
        float xv = __ldg(&xr[k]);
        float4 w = __ldg((const float4*)(W1 + k * 128 + lane * 4));
        acc[0] += xv * w.x; acc[1] += xv * w.y; acc[2] += xv * w.z; acc[3] += xv * w.w;
    }
    __half2 h0 = __floats2half2_rn(acc[0], acc[1]);
    __half2 h1 = __floats2half2_rn(acc[2], acc[3]);
    uint2 st;
    st.x = *(unsigned*)&h0; st.y = *(unsigned*)&h1;
    *(uint2*)(g_hlinh + node * 128 + lane * 4) = st;
    float pS = 0.f, pD = 0.f;
#pragma unroll
    for (int j = 0; j < 4; j++) {
        pS += acc[j] * __ldg(&aS[lane * 4 + j]);
        pD += acc[j] * __ldg(&aD[lane * 4 + j]);
    }
#pragma unroll
    for (int o = 1; o < 8; o <<= 1) {
        pS += __shfl_xor_sync(FULLM, pS, o);
        pD += __shfl_xor_sync(FULLM, pD, o);
    }
    if ((lane & 7) == 0) {
        int h = lane >> 3;
        g_als[node * 4 + h] = pS;
        g_ald[node * 4 + h] = pD;
    }
}

// ----------------------------- 128 -> OUTC GEMM (FFMA2) + fused BN-in + als epilogue --------
template <int OUTC>
__global__ void gemm_kernel(const float* __restrict__ W,
                            const float* __restrict__ aS, const float* __restrict__ aD,
                            const float* __restrict__ bnG, const float* __restrict__ bnBe) {
    constexpr int CJ2 = OUTC / 64;
    __shared__ float As[64][33];
    __shared__ unsigned long long Ws2[32][OUTC / 2];
    __shared__ float sScale[128], sShift[128];
    int t = threadIdx.x;   // 256
    int tc = t & 31;
    int tn = t >> 5;
    int nodeBase = blockIdx.x * 64;

    if (t < 128) {
        const float invN = 1.f / (float)N_NODES;
        float mu = g_bnsum[t] * invN;
        float var = g_bnsum[128 + t] * invN - mu * mu;
        float rs = rsqrtf(var + EPS_BN);
        float sc = rs * __ldg(&bnG[t]);
        sScale[t] = sc;
        sShift[t] = __ldg(&bnBe[t]) - mu * sc;
    }

    unsigned long long acc[8][CJ2];
#pragma unroll
    for (int r = 0; r < 8; r++)
#pragma unroll
        for (int cj = 0; cj < CJ2; cj++) acc[r][cj] = 0ull;

    const float2* Wp = (const float2*)W;
    __syncthreads();
    for (int kc = 0; kc < 4; kc++) {
#pragma unroll
        for (int j = 0; j < 8; j++) {
            int idx = t + j * 256;
            int row = idx >> 5, col = idx & 31;
            int node = nodeBase + row;
            int c = kc * 32 + col;
            float v = 0.f;
            if (node < N_NODES)
                v = eluf(g_feat[node * 128 + c] * sScale[c] + sShift[c]);
            As[row][col] = v;
        }
#pragma unroll
        for (int j = 0; j < (32 * OUTC / 2) / 256; j++) {
            int idx = t + j * 256;
            int r = idx / (OUTC / 2), c2 = idx % (OUTC / 2);
            float2 w = __ldg(&Wp[(kc * 32 + r) * (OUTC / 2) + c2]);
            Ws2[r][c2] = pack2(w.x, w.y);
        }
        __syncthreads();
#pragma unroll
        for (int kk = 0; kk < 32; kk++) {
            unsigned long long w[CJ2];
#pragma unroll
            for (int cj = 0; cj < CJ2; cj++) w[cj] = Ws2[kk][tc + 32 * cj];
#pragma unroll
            for (int r = 0; r < 8; r++) {
                float a = As[tn * 8 + r][kk];
                unsigned long long a2 = pack2(a, a);
#pragma unroll
                for (int cj = 0; cj < CJ2; cj++) FMA_F32X2(acc[r][cj], a2, w[cj]);
            }
        }
        __syncthreads();
    }

#pragma unroll
    for (int r = 0; r < 8; r++) {
        int node = nodeBase + tn * 8 + r;
        if (node >= N_NODES) continue;
        __half2* outp = (__half2*)(g_hlinh + node * OUTC);
        float2 f[CJ2];
#pragma unroll
        for (int cj = 0; cj < CJ2; cj++) {
            f[cj] = unpack2(acc[r][cj]);
            outp[tc + 32 * cj] = __floats2half2_rn(f[cj].x, f[cj].y);
        }
        if (OUTC == 128) {
            float pS0 = f[0].x * __ldg(&aS[2 * tc]) + f[0].y * __ldg(&aS[2 * tc + 1]);
            float pD0 = f[0].x * __ldg(&aD[2 * tc]) + f[0].y * __ldg(&aD[2 * tc + 1]);
            float pS1 = f[CJ2 - 1].x * __ldg(&aS[64 + 2 * tc]) + f[CJ2 - 1].y * __ldg(&aS[64 + 2 * tc + 1]);
            float pD1 = f[CJ2 - 1].x * __ldg(&aD[64 + 2 * tc]) + f[CJ2 - 1].y * __ldg(&aD[64 + 2 * tc + 1]);
#pragma unroll
            for (int o = 1; o < 16; o <<= 1) {
                pS0 += __shfl_xor_sync(FULLM, pS0, o);
                pD0 += __shfl_xor_sync(FULLM, pD0, o);
                pS1 += __shfl_xor_sync(FULLM, pS1, o);
                pD1 += __shfl_xor_sync(FULLM, pD1, o);
            }
            if ((tc & 15) == 0) {
                int hg = tc >> 4;
                g_als[node * 4 + hg] = pS0;
                g_ald[node * 4 + hg] = pD0;
                g_als[node * 4 + 2 + hg] = pS1;
                g_ald[node * 4 + 2 + hg] = pD1;
            }
        } else {
            float pS = f[0].x * __ldg(&aS[2 * tc]) + f[0].y * __ldg(&aS[2 * tc + 1]);
            float pD = f[0].x * __ldg(&aD[2 * tc]) + f[0].y * __ldg(&aD[2 * tc + 1]);
#pragma unroll
            for (int o = 1; o < 32; o <<= 1) {
                pS += __shfl_xor_sync(FULLM, pS, o);
                pD += __shfl_xor_sync(FULLM, pD, o);
            }
            if (tc == 0) {
                g_als[node] = pS;
                g_ald[node] = pD;
            }
        }
    }
}

// ----------------------------- GAT aggregation v2: chunked two-phase, high MLP ---------------
// warp per node. Phase 1 (per 32-edge chunk): lane <-> edge; coalesced csr load,
// one LDG.128 per lane for all-head logits, warp-reduced chunk max/sum, one rescale per chunk.
// Phase 2: lane <-> channel group; value gathers issued in unroll-8 batches (MLP=8).
template <int H, int HC, bool ELU_OUT>
__global__ void attn_kernel(const float* __restrict__ bias) {
    constexpr int K = HC / 32;          // channels per lane (4 or 2)
    constexpr int C = HC / H;
    int node = (blockIdx.x * blockDim.x + threadIdx.x) >> 5;
    int lane = threadIdx.x & 31;
    if (node >= N_NODES) return;
    const int h0 = (lane * K) / C;      // this lane's head (uniform across its K channels)

    float ald[H];
    if (H == 4) {
        float4 q = *(const float4*)(g_ald + node * 4);
        ald[0] = q.x; ald[1] = q.y; ald[2] = q.z; ald[3] = q.w;
    } else {
        ald[0] = g_ald[node];
    }

    float m[H], s[H], acc[K];
#pragma unroll
    for (int h = 0; h < H; h++) { m[h] = __int_as_float(0xff800000); s[h] = 0.f; }
#pragma unroll
    for (int k = 0; k < K; k++) acc[k] = 0.f;

    int beg = g_off[node], end = g_off[node + 1];
    for (int base = beg; base < end; base += 32) {
        int cnt = min(32, end - base);
        int srcl = (lane < cnt) ? __ldg(&g_csr[base + lane]) : 0;

        // ---- phase 1: logits for my edge, all heads ----
        float e[H];
        if (H == 4) {
            if (lane < cnt) {
                float4 q = __ldg((const float4*)(g_als + srcl * 4));
                e[0] = lrelu(q.x + ald[0]); e[1] = lrelu(q.y + ald[1]);
                e[2] = lrelu(q.z + ald[2]); e[3] = lrelu(q.w + ald[3]);
            } else {
#pragma unroll
                for (int h = 0; h < 4; h++) e[h] = __int_as_float(0xff800000);
            }
        } else {
            e[0] = (lane < cnt) ? lrelu(__ldg(&g_als[srcl]) + ald[0])
                                : __int_as_float(0xff800000);
        }
        // chunk max per head
        float sch[H], pm[H];
#pragma unroll
        for (int h = 0; h < H; h++) {
            float cm = e[h];
#pragma unroll
            for (int o = 16; o; o >>= 1) cm = fmaxf(cm, __shfl_xor_sync(FULLM, cm, o));
            float nm = fmaxf(m[h], cm);
            sch[h] = __expf(m[h] - nm);     // 0 on first chunk
            m[h] = nm;
            pm[h] = __expf(e[h] - nm);      // inactive lanes -> 0
            float ps = pm[h];
#pragma unroll
            for (int o = 16; o; o >>= 1) ps += __shfl_xor_sync(FULLM, ps, o);
            s[h] = s[h] * sch[h] + ps;
        }
        // rescale accumulators by my head's factor
        float sc0;
        if (H == 4) sc0 = (h0 == 0) ? sch[0] : (h0 == 1) ? sch[1] : (h0 == 2) ? sch[2] : sch[3];
        else sc0 = sch[0];
#pragma unroll
        for (int k = 0; k < K; k++) acc[k] *= sc0;

        // ---- phase 2: value gathers, sub-batches of 8 for MLP ----
        for (int j0 = 0; j0 < cnt; j0 += 8) {
            uint2 q4[8]; unsigned q2[8]; float pj[8];
#pragma unroll
            for (int u = 0; u < 8; u++) {
                int j = j0 + u;
                bool val = j < cnt;
                int jj = j & 31;
                int src = __shfl_sync(FULLM, srcl, jj);
                float p;
                if (H == 4) {
                    float v0 = __shfl_sync(FULLM, pm[0], jj);
                    float v1 = __shfl_sync(FULLM, pm[1], jj);
                    float v2 = __shfl_sync(FULLM, pm[2], jj);
                    float v3 = __shfl_sync(FULLM, pm[3], jj);
                    p = (h0 == 0) ? v0 : (h0 == 1) ? v1 : (h0 == 2) ? v2 : v3;
                } else {
                    p = __shfl_sync(FULLM, pm[0], jj);
                }
                pj[u] = val ? p : 0.f;
                if (K == 4) {
                    q4[u] = val ? *(const uint2*)(g_hlinh + (size_t)src * HC + lane * 4)
                                : make_uint2(0u, 0u);
                } else {
                    q2[u] = val ? *(const unsigned*)(g_hlinh + (size_t)src * HC + lane * 2) : 0u;
                }
            }
#pragma unroll
            for (int u = 0; u < 8; u++) {
                if (K == 4) {
                    float2 f0 = __half22float2(*(__half2*)&q4[u].x);
                    float2 f1 = __half22float2(*(__half2*)&q4[u].y);
                    acc[0] += pj[u] * f0.x; acc[1] += pj[u] * f0.y;
                    acc[2] += pj[u] * f1.x; acc[3] += pj[u] * f1.y;
                } else {
                    float2 f0 = __half22float2(*(__half2*)&q2[u]);
                    acc[0] += pj[u] * f0.x; acc[1] += pj[u] * f0.y;
                }
            }
        }
    }

    float sH;
    if (H == 4) sH = (h0 == 0) ? s[0] : (h0 == 1) ? s[1] : (h0 == 2) ? s[2] : s[3];
    else sH = s[0];
    float inv = 1.f / (sH + 1e-16f);
    if (K == 4) {
        float4 o;
        o.x = acc[0] * inv + __ldg(&bias[lane * 4 + 0]);
        o.y = acc[1] * inv + __ldg(&bias[lane * 4 + 1]);
        o.z = acc[2] * inv + __ldg(&bias[lane * 4 + 2]);
        o.w = acc[3] * inv + __ldg(&bias[lane * 4 + 3]);
        if (ELU_OUT) { o.x = eluf(o.x); o.y = eluf(o.y); o.z = eluf(o.z); o.w = eluf(o.w); }
        *(float4*)(g_feat + node * HC + lane * 4) = o;
    } else {
        float2 o;
        o.x = acc[0] * inv + __ldg(&bias[lane * 2 + 0]);
        o.y = acc[1] * inv + __ldg(&bias[lane * 2 + 1]);
        if (ELU_OUT) { o.x = eluf(o.x); o.y = eluf(o.y); }
        *(float2*)(g_feat + node * HC + lane * 2) = o;
    }
}

// ----------------------------- batch norm stats -----------------------------
__global__ void zero_bnsum_kernel() {
    if (threadIdx.x < 256) g_bnsum[threadIdx.x] = 0.f;
}

__global__ void bnstats_kernel() {
    int c = threadIdx.x;  // 128
    int n0 = blockIdx.x * 128;
    float s = 0.f, sq = 0.f;
    for (int r = 0; r < 128; r++) {
        int n = n0 + r;
        if (n < N_NODES) {
            float v = g_feat[n * 128 + c];
            s += v;
            sq += v * v;
        }
    }
    atomicAdd(&g_bnsum[c], s);
    atomicAdd(&g_bnsum[128 + c], sq);
}

// ----------------------------- pooling (batch sorted) -----------------------------
__device__ __forceinline__ int lower_bound_batch(int key) {
    int lo = 0, hi = N_NODES;
    while (lo < hi) {
        int mid = (lo + hi) >> 1;
        if (g_batch[mid] < key) lo = mid + 1;
        else hi = mid;
    }
    return lo;
}

__global__ void pool_kernel() {
    int gidx = blockIdx.x;
    __shared__ int se[2];
    if (threadIdx.x == 0) se[0] = lower_bound_batch(gidx);
    if (threadIdx.x == 1) se[1] = lower_bound_batch(gidx + 1);
    __syncthreads();
    int beg = se[0], end = se[1];
    int c = threadIdx.x & 63, sl = threadIdx.x >> 6;
    float sum = 0.f, mx = __int_as_float(0xff800000);
    for (int n = beg + sl; n < end; n += 2) {
        float v = g_feat[n * 64 + c];
        sum += v;
        mx = fmaxf(mx, v);
    }
    __shared__ float shs[128], shm[128];
    shs[threadIdx.x] = sum;
    shm[threadIdx.x] = mx;
    __syncthreads();
    if (sl == 0) {
        sum += shs[64 + c];
        mx = fmaxf(mx, shm[64 + c]);
        int cnt = end - beg;
        float mean = (cnt > 0) ? sum / (float)cnt : 0.f;
        float maxv = (cnt > 0) ? mx : 0.f;
        g_pool[gidx * 128 + c] = mean;
        g_pool[gidx * 128 + 64 + c] = maxv;
    }
}

// ----------------------------- classifier -----------------------------
__global__ void final_kernel(const float* __restrict__ fc1w, const float* __restrict__ fc1b,
                             const float* __restrict__ fc2w, const float* __restrict__ fc2b,
                             float* __restrict__ out) {
    int gidx = blockIdx.x;
    int c = threadIdx.x;  // 64
    __shared__ float hg[128];
    hg[c] = g_pool[gidx * 128 + c];
    hg[c + 64] = g_pool[gidx * 128 + 64 + c];
    __syncthreads();
    float acc = __ldg(&fc1b[c]);
#pragma unroll 8
    for (int k = 0; k < 128; k++) acc += hg[k] * __ldg(&fc1w[k * 64 + c]);
    float z = eluf(acc);
    float part = z * __ldg(&fc2w[c]);
#pragma unroll
    for (int off = 16; off; off >>= 1) part += __shfl_xor_sync(FULLM, part, off);
    __shared__ float warpsum[2];
    if ((c & 31) == 0) warpsum[c >> 5] = part;
    __syncthreads();
    if (c == 0) out[gidx] = warpsum[0] + warpsum[1] + __ldg(&fc2b[0]);
}

// ----------------------------- launch -----------------------------
extern "C" void kernel_launch(void* const* d_in, const int* in_sizes, int n_in,
                              void* d_out, int out_size) {
    const float* x      = (const float*)d_in[0];
    const void*  ei     = d_in[1];
    const void*  batch  = d_in[2];
    const float* W1     = (const float*)d_in[3];
    const float* a1_src = (const float*)d_in[4];
    const float* a1_dst = (const float*)d_in[5];
    const float* b1     = (const float*)d_in[6];
    const float* g1     = (const float*)d_in[7];
    const float* be1    = (const float*)d_in[8];
    const float* W2     = (const float*)d_in[9];
    const float* a2_src = (const float*)d_in[10];
    const float* a2_dst = (const float*)d_in[11];
    const float* b2     = (const float*)d_in[12];
    const float* g2     = (const float*)d_in[13];
    const float* be2    = (const float*)d_in[14];
    const float* W3     = (const float*)d_in[15];
    const float* a3_src = (const float*)d_in[16];
    const float* a3_dst = (const float*)d_in[17];
    const float* b3     = (const float*)d_in[18];
    const float* fc1_w  = (const float*)d_in[19];
    const float* fc1_b  = (const float*)d_in[20];
    const float* fc2_w  = (const float*)d_in[21];
    const float* fc2_b  = (const float*)d_in[22];
    float* out = (float*)d_out;

    const int EB = (E_TOT + 255) / 256;
    const int ATTN_B = (N_NODES + 7) / 8;
    const int GEMM_B = (N_NODES + 63) / 64;

    // graph structure (CSR by dst)
    detect_kernel<<<1, 256>>>(ei);
    zero_deg_kernel<<<(N_NODES + 255) / 256, 256>>>();
    convert_kernel<<<EB, 256>>>(ei, batch);
    scan_partial_kernel<<<SCAN_B, 512>>>();
    scan_mid_kernel<<<1, 128>>>();
    scan_final_kernel<<<SCAN_B, 512>>>();
    fill_kernel<<<EB, 256>>>();

    // ---- layer 1 ----
    gemm1_kernel<<<(N_NODES + 7) / 8, 256>>>(x, W1, a1_src, a1_dst);
    attn_kernel<4, 128, false><<<ATTN_B, 256>>>(b1);
    zero_bnsum_kernel<<<1, 256>>>();
    bnstats_kernel<<<(N_NODES + 127) / 128, 128>>>();

    // ---- layer 2 ----
    gemm_kernel<128><<<GEMM_B, 256>>>(W2, a2_src, a2_dst, g1, be1);
    attn_kernel<4, 128, false><<<ATTN_B, 256>>>(b2);
    zero_bnsum_kernel<<<1, 256>>>();
    bnstats_kernel<<<(N_NODES + 127) / 128, 128>>>();

    // ---- layer 3 ----
    gemm_kernel<64><<<GEMM_B, 256>>>(W3, a3_src, a3_dst, g2, be2);
    attn_kernel<1, 64, true><<<ATTN_B, 256>>>(b3);

    // ---- readout ----
    pool_kernel<<<N_GRAPHS, 128>>>();
    final_kernel<<<N_GRAPHS, 64>>>(fc1_w, fc1_b, fc2_w, fc2_b, out);
}

// round 5
// speedup vs baseline: 1.2068x; 1.2068x over previous
#include <cuda_runtime.h>
#include <cuda_fp16.h>
#include <cstdint>

#define N_NODES 100000
#define N_EDGES 1600000
#define E_TOT   (N_EDGES + N_NODES)   // self loops appended
#define N_GRAPHS 1024
#define EPS_BN 1e-5f
#define SCAN_B 98                      // ceil(N_NODES / 1024)
#define FULLM 0xffffffffu

// ----------------------------- scratch (device globals) -----------------------------
__device__ int    g_is64;
__device__ int    g_src[E_TOT];
__device__ int    g_dst[E_TOT];
__device__ int    g_batch[N_NODES];
__device__ int    g_deg[N_NODES];
__device__ int    g_off[N_NODES + 1];
__device__ int    g_cur[N_NODES];
__device__ int    g_csr[E_TOT];
__device__ int    g_bsum[SCAN_B];
__device__ __half g_hlinh[N_NODES * 128];  // post-GEMM features, fp16 (attn gather input)
__device__ float  g_feat[N_NODES * 128];   // attn output (raw, pre-BN) / GEMM input
__device__ float  g_als[N_NODES * 4];
__device__ float  g_ald[N_NODES * 4];
__device__ float  g_bnsum[256];            // [0:128) sum, [128:256) sumsq
__device__ float  g_pool[N_GRAPHS * 128];  // mean (0..63) || max (64..127)

// ----------------------------- utility -----------------------------
__device__ __forceinline__ float eluf(float v) { return v > 0.f ? v : expm1f(v); }
__device__ __forceinline__ float lrelu(float v) { return v > 0.f ? v : 0.2f * v; }

__device__ __forceinline__ unsigned long long pack2(float x, float y) {
    unsigned long long r;
    asm("mov.b64 %0, {%1, %2};" : "=l"(r) : "f"(x), "f"(y));
    return r;
}
__device__ __forceinline__ float2 unpack2(unsigned long long v) {
    float2 r;
    asm("mov.b64 {%0, %1}, %2;" : "=f"(r.x), "=f"(r.y) : "l"(v));
    return r;
}
#define FMA_F32X2(acc, a, b) \
    asm("fma.rn.f32x2 %0, %1, %2, %0;" : "+l"(acc) : "l"(a), "l"(b))

// ----------------------------- dtype detection -----------------------------
__global__ void detect_kernel(const void* ei) {
    __shared__ int any;
    if (threadIdx.x == 0) any = 0;
    __syncthreads();
    const int* p = (const int*)ei;
    int local = 0;
    for (int i = threadIdx.x; i < 2048; i += 256)
        if (p[2 * i + 1] != 0) local = 1;
    if (local) atomicOr(&any, 1);
    __syncthreads();
    if (threadIdx.x == 0) g_is64 = any ? 0 : 1;
}

__global__ void zero_deg_kernel() {
    int i = blockIdx.x * 256 + threadIdx.x;
    if (i < N_NODES) g_deg[i] = 0;
}

__global__ void convert_kernel(const void* ei, const void* batch) {
    int i = blockIdx.x * 256 + threadIdx.x;
    int is64 = g_is64;
    if (i < E_TOT) {
        int s, d;
        if (i < N_EDGES) {
            if (is64) {
                s = (int)((const long long*)ei)[i];
                d = (int)((const long long*)ei)[N_EDGES + i];
            } else {
                s = ((const int*)ei)[i];
                d = ((const int*)ei)[N_EDGES + i];
            }
        } else {
            s = d = i - N_EDGES;
        }
        g_src[i] = s;
        g_dst[i] = d;
        atomicAdd(&g_deg[d], 1);
    }
    if (i < N_NODES) {
        g_batch[i] = is64 ? (int)((const long long*)batch)[i] : ((const int*)batch)[i];
    }
}

// ----------------------------- hierarchical exclusive scan -----------------------------
__global__ void scan_partial_kernel() {
    __shared__ int sh[512];
    int t = threadIdx.x;
    int base = blockIdx.x * 1024;
    int i0 = base + t, i1 = base + 512 + t;
    int v = ((i0 < N_NODES) ? g_deg[i0] : 0) + ((i1 < N_NODES) ? g_deg[i1] : 0);
    sh[t] = v;
    __syncthreads();
    for (int o = 256; o; o >>= 1) {
        if (t < o) sh[t] += sh[t + o];
        __syncthreads();
    }
    if (t == 0) g_bsum[blockIdx.x] = sh[0];
}

__global__ void scan_mid_kernel() {
    __shared__ int sh[128];
    int t = threadIdx.x;
    int orig = (t < SCAN_B) ? g_bsum[t] : 0;
    sh[t] = orig;
    __syncthreads();
    for (int o = 1; o < 128; o <<= 1) {
        int v = (t >= o) ? sh[t - o] : 0;
        __syncthreads();
        sh[t] += v;
        __syncthreads();
    }
    if (t < SCAN_B) g_bsum[t] = sh[t] - orig;
    if (t == 0) g_off[N_NODES] = E_TOT;
}

__global__ void scan_final_kernel() {
    __shared__ int wsum[16];
    int t = threadIdx.x;
    int base = blockIdx.x * 1024;
    int i0 = base + 2 * t, i1 = i0 + 1;
    int d0 = (i0 < N_NODES) ? g_deg[i0] : 0;
    int d1 = (i1 < N_NODES) ? g_deg[i1] : 0;
    int tsum = d0 + d1;
    int lane = t & 31, wid = t >> 5;
    int v = tsum;
#pragma unroll
    for (int o = 1; o < 32; o <<= 1) {
        int u = __shfl_up_sync(FULLM, v, o);
        if (lane >= o) v += u;
    }
    if (lane == 31) wsum[wid] = v;
    __syncthreads();
    if (t < 16) {
        int w = wsum[t];
#pragma unroll
        for (int o = 1; o < 16; o <<= 1) {
            int u = __shfl_up_sync(0xffffu, w, o);
            if (t >= o) w += u;
        }
        wsum[t] = w;
    }
    __syncthreads();
    int excl = v - tsum + (wid ? wsum[wid - 1] : 0) + g_bsum[blockIdx.x];
    if (i0 < N_NODES) { g_off[i0] = excl;      g_cur[i0] = excl; }
    if (i1 < N_NODES) { g_off[i1] = excl + d0; g_cur[i1] = excl + d0; }
}

__global__ void fill_kernel() {
    int i = blockIdx.x * 256 + threadIdx.x;
    if (i < E_TOT) {
        int p = atomicAdd(&g_cur[g_dst[i]], 1);
        g_csr[p] = g_src[i];
    }
}

// ----------------------------- layer-1 GEMM (5 -> 128) + als epilogue -----------------------
__global__ void gemm1_kernel(const float* __restrict__ x, const float* __restrict__ W1,
                             const float* __restrict__ aS, const float* __restrict__ aD) {
    int node = blockIdx.x * 8 + (threadIdx.x >> 5);
    int lane = threadIdx.x & 31;
    if (node >= N_NODES) return;
    float acc[4] = {0.f, 0.f, 0.f, 0.f};
    const float* xr = x + node * 5;
#pragma unroll
    for (int k = 0; k < 5; k++) {
        float xv = __ldg(&xr[k]);
        float4 w = __ldg((const float4*)(W1 + k * 128 + lane * 4));
        acc[0] += xv * w.x; acc[1] += xv * w.y; acc[2] += xv * w.z; acc[3] += xv * w.w;
    }
    __half2 h0 = __floats2half2_rn(acc[0], acc[1]);
    __half2 h1 = __floats2half2_rn(acc[2], acc[3]);
    uint2 st;
    st.x = *(unsigned*)&h0; st.y = *(unsigned*)&h1;
    *(uint2*)(g_hlinh + node * 128 + lane * 4) = st;
    float pS = 0.f, pD = 0.f;
#pragma unroll
    for (int j = 0; j < 4; j++) {
        pS += acc[j] * __ldg(&aS[lane * 4 + j]);
        pD += acc[j] * __ldg(&aD[lane * 4 + j]);
    }
#pragma unroll
    for (int o = 1; o < 8; o <<= 1) {
        pS += __shfl_xor_sync(FULLM, pS, o);
        pD += __shfl_xor_sync(FULLM, pD, o);
    }
    if ((lane & 7) == 0) {
        int h = lane >> 3;
        g_als[node * 4 + h] = pS;
        g_ald[node * 4 + h] = pD;
    }
}

// ----------------------------- 128 -> OUTC GEMM (FFMA2) + fused BN-in + als epilogue --------
template <int OUTC>
__global__ void gemm_kernel(const float* __restrict__ W,
                            const float* __restrict__ aS, const float* __restrict__ aD,
                            const float* __restrict__ bnG, const float* __restrict__ bnBe) {
    constexpr int CJ2 = OUTC / 64;
    __shared__ float As[64][33];
    __shared__ unsigned long long Ws2[32][OUTC / 2];
    __shared__ float sScale[128], sShift[128];
    int t = threadIdx.x;   // 256
    int tc = t & 31;
    int tn = t >> 5;
    int nodeBase = blockIdx.x * 64;

    if (t < 128) {
        const float invN = 1.f / (float)N_NODES;
        float mu = g_bnsum[t] * invN;
        float var = g_bnsum[128 + t] * invN - mu * mu;
        float rs = rsqrtf(var + EPS_BN);
        float sc = rs * __ldg(&bnG[t]);
        sScale[t] = sc;
        sShift[t] = __ldg(&bnBe[t]) - mu * sc;
    }

    unsigned long long acc[8][CJ2];
#pragma unroll
    for (int r = 0; r < 8; r++)
#pragma unroll
        for (int cj = 0; cj < CJ2; cj++) acc[r][cj] = 0ull;

    const float2* Wp = (const float2*)W;
    __syncthreads();
    for (int kc = 0; kc < 4; kc++) {
#pragma unroll
        for (int j = 0; j < 8; j++) {
            int idx = t + j * 256;
            int row = idx >> 5, col = idx & 31;
            int node = nodeBase + row;
            int c = kc * 32 + col;
            float v = 0.f;
            if (node < N_NODES)
                v = eluf(g_feat[node * 128 + c] * sScale[c] + sShift[c]);
            As[row][col] = v;
        }
#pragma unroll
        for (int j = 0; j < (32 * OUTC / 2) / 256; j++) {
            int idx = t + j * 256;
            int r = idx / (OUTC / 2), c2 = idx % (OUTC / 2);
            float2 w = __ldg(&Wp[(kc * 32 + r) * (OUTC / 2) + c2]);
            Ws2[r][c2] = pack2(w.x, w.y);
        }
        __syncthreads();
#pragma unroll
        for (int kk = 0; kk < 32; kk++) {
            unsigned long long w[CJ2];
#pragma unroll
            for (int cj = 0; cj < CJ2; cj++) w[cj] = Ws2[kk][tc + 32 * cj];
#pragma unroll
            for (int r = 0; r < 8; r++) {
                float a = As[tn * 8 + r][kk];
                unsigned long long a2 = pack2(a, a);
#pragma unroll
                for (int cj = 0; cj < CJ2; cj++) FMA_F32X2(acc[r][cj], a2, w[cj]);
            }
        }
        __syncthreads();
    }

#pragma unroll
    for (int r = 0; r < 8; r++) {
        int node = nodeBase + tn * 8 + r;
        if (node >= N_NODES) continue;
        __half2* outp = (__half2*)(g_hlinh + node * OUTC);
        float2 f[CJ2];
#pragma unroll
        for (int cj = 0; cj < CJ2; cj++) {
            f[cj] = unpack2(acc[r][cj]);
            outp[tc + 32 * cj] = __floats2half2_rn(f[cj].x, f[cj].y);
        }
        if (OUTC == 128) {
            float pS0 = f[0].x * __ldg(&aS[2 * tc]) + f[0].y * __ldg(&aS[2 * tc + 1]);
            float pD0 = f[0].x * __ldg(&aD[2 * tc]) + f[0].y * __ldg(&aD[2 * tc + 1]);
            float pS1 = f[CJ2 - 1].x * __ldg(&aS[64 + 2 * tc]) + f[CJ2 - 1].y * __ldg(&aS[64 + 2 * tc + 1]);
            float pD1 = f[CJ2 - 1].x * __ldg(&aD[64 + 2 * tc]) + f[CJ2 - 1].y * __ldg(&aD[64 + 2 * tc + 1]);
#pragma unroll
            for (int o = 1; o < 16; o <<= 1) {
                pS0 += __shfl_xor_sync(FULLM, pS0, o);
                pD0 += __shfl_xor_sync(FULLM, pD0, o);
                pS1 += __shfl_xor_sync(FULLM, pS1, o);
                pD1 += __shfl_xor_sync(FULLM, pD1, o);
            }
            if ((tc & 15) == 0) {
                int hg = tc >> 4;
                g_als[node * 4 + hg] = pS0;
                g_ald[node * 4 + hg] = pD0;
                g_als[node * 4 + 2 + hg] = pS1;
                g_ald[node * 4 + 2 + hg] = pD1;
            }
        } else {
            float pS = f[0].x * __ldg(&aS[2 * tc]) + f[0].y * __ldg(&aS[2 * tc + 1]);
            float pD = f[0].x * __ldg(&aD[2 * tc]) + f[0].y * __ldg(&aD[2 * tc + 1]);
#pragma unroll
            for (int o = 1; o < 32; o <<= 1) {
                pS += __shfl_xor_sync(FULLM, pS, o);
                pD += __shfl_xor_sync(FULLM, pD, o);
            }
            if (tc == 0) {
                g_als[node] = pS;
                g_ald[node] = pD;
            }
        }
    }
}

// ----------------------------- GAT aggregation v4: no-max softmax, width-8 ILP ---------------
// Softmax is shift-invariant; logits here are structurally bounded (|e| << 88), so we skip
// the running max entirely. Edges processed in width-8 batches: all loads independent
// (MLP=8), no cross-iteration dependency chain.
template <int H, int HC, bool ELU_OUT>
__global__ void attn_kernel(const float* __restrict__ bias) {
    constexpr int K = HC / 32;          // channels per lane (4 or 2)
    constexpr int C = HC / H;
    constexpr int UW = 8;               // batch width
    int node = (blockIdx.x * blockDim.x + threadIdx.x) >> 5;
    int lane = threadIdx.x & 31;
    if (node >= N_NODES) return;
    const int h0 = (lane * K) / C;      // this lane's head

    float ad = g_ald[node * H + h0];
    float s = 0.f;
    float acc[K];
#pragma unroll
    for (int k = 0; k < K; k++) acc[k] = 0.f;

    int beg = g_off[node], end = g_off[node + 1];
    for (int base = beg; base < end; base += UW) {
        int srcu[UW];
        float alsu[UW];
        uint2 q4[UW];
        unsigned q2[UW];
        // stage 1: consecutive csr loads (broadcast across lanes), predicated
#pragma unroll
        for (int u = 0; u < UW; u++)
            srcu[u] = (base + u < end) ? __ldg(&g_csr[base + u]) : 0;
        // stage 2: independent logit loads (invalid -> -1e30 => exp -> 0)
#pragma unroll
        for (int u = 0; u < UW; u++)
            alsu[u] = (base + u < end) ? __ldg(&g_als[srcu[u] * H + h0]) : -1e30f;
        // stage 3: independent feature vector loads
#pragma unroll
        for (int u = 0; u < UW; u++) {
            if (K == 4)
                q4[u] = (base + u < end) ? *(const uint2*)(g_hlinh + (size_t)srcu[u] * HC + lane * 4)
                                         : make_uint2(0u, 0u);
            else
                q2[u] = (base + u < end) ? *(const unsigned*)(g_hlinh + (size_t)srcu[u] * HC + lane * 2)
                                         : 0u;
        }
        // stage 4: exp + accumulate (independent exps; short FMA chains)
#pragma unroll
        for (int u = 0; u < UW; u++) {
            float p = __expf(lrelu(alsu[u] + ad));
            s += p;
            if (K == 4) {
                float2 f0 = __half22float2(*(__half2*)&q4[u].x);
                float2 f1 = __half22float2(*(__half2*)&q4[u].y);
                acc[0] += p * f0.x; acc[1] += p * f0.y;
                acc[2] += p * f1.x; acc[3] += p * f1.y;
            } else {
                float2 f0 = __half22float2(*(__half2*)&q2[u]);
                acc[0] += p * f0.x; acc[1] += p * f0.y;
            }
        }
    }

    float inv = 1.f / (s + 1e-16f);
    if (K == 4) {
        float4 o;
        o.x = acc[0] * inv + __ldg(&bias[lane * 4 + 0]);
        o.y = acc[1] * inv + __ldg(&bias[lane * 4 + 1]);
        o.z = acc[2] * inv + __ldg(&bias[lane * 4 + 2]);
        o.w = acc[3] * inv + __ldg(&bias[lane * 4 + 3]);
        if (ELU_OUT) { o.x = eluf(o.x); o.y = eluf(o.y); o.z = eluf(o.z); o.w = eluf(o.w); }
        *(float4*)(g_feat + node * HC + lane * 4) = o;
    } else {
        float2 o;
        o.x = acc[0] * inv + __ldg(&bias[lane * 2 + 0]);
        o.y = acc[1] * inv + __ldg(&bias[lane * 2 + 1]);
        if (ELU_OUT) { o.x = eluf(o.x); o.y = eluf(o.y); }
        *(float2*)(g_feat + node * HC + lane * 2) = o;
    }
}

// ----------------------------- batch norm stats -----------------------------
__global__ void zero_bnsum_kernel() {
    if (threadIdx.x < 256) g_bnsum[threadIdx.x] = 0.f;
}

__global__ void bnstats_kernel() {
    int c = threadIdx.x;  // 128
    int n0 = blockIdx.x * 128;
    float s = 0.f, sq = 0.f;
    for (int r = 0; r < 128; r++) {
        int n = n0 + r;
        if (n < N_NODES) {
            float v = g_feat[n * 128 + c];
            s += v;
            sq += v * v;
        }
    }
    atomicAdd(&g_bnsum[c], s);
    atomicAdd(&g_bnsum[128 + c], sq);
}

// ----------------------------- pooling (batch sorted) -----------------------------
__device__ __forceinline__ int lower_bound_batch(int key) {
    int lo = 0, hi = N_NODES;
    while (lo < hi) {
        int mid = (lo + hi) >> 1;
        if (g_batch[mid] < key) lo = mid + 1;
        else hi = mid;
    }
    return lo;
}

__global__ void pool_kernel() {
    int gidx = blockIdx.x;
    __shared__ int se[2];
    if (threadIdx.x == 0) se[0] = lower_bound_batch(gidx);
    if (threadIdx.x == 1) se[1] = lower_bound_batch(gidx + 1);
    __syncthreads();
    int beg = se[0], end = se[1];
    int c = threadIdx.x & 63, sl = threadIdx.x >> 6;
    float sum = 0.f, mx = __int_as_float(0xff800000);
    for (int n = beg + sl; n < end; n += 2) {
        float v = g_feat[n * 64 + c];
        sum += v;
        mx = fmaxf(mx, v);
    }
    __shared__ float shs[128], shm[128];
    shs[threadIdx.x] = sum;
    shm[threadIdx.x] = mx;
    __syncthreads();
    if (sl == 0) {
        sum += shs[64 + c];
        mx = fmaxf(mx, shm[64 + c]);
        int cnt = end - beg;
        float mean = (cnt > 0) ? sum / (float)cnt : 0.f;
        float maxv = (cnt > 0) ? mx : 0.f;
        g_pool[gidx * 128 + c] = mean;
        g_pool[gidx * 128 + 64 + c] = maxv;
    }
}

// ----------------------------- classifier -----------------------------
__global__ void final_kernel(const float* __restrict__ fc1w, const float* __restrict__ fc1b,
                             const float* __restrict__ fc2w, const float* __restrict__ fc2b,
                             float* __restrict__ out) {
    int gidx = blockIdx.x;
    int c = threadIdx.x;  // 64
    __shared__ float hg[128];
    hg[c] = g_pool[gidx * 128 + c];
    hg[c + 64] = g_pool[gidx * 128 + 64 + c];
    __syncthreads();
    float acc = __ldg(&fc1b[c]);
#pragma unroll 8
    for (int k = 0; k < 128; k++) acc += hg[k] * __ldg(&fc1w[k * 64 + c]);
    float z = eluf(acc);
    float part = z * __ldg(&fc2w[c]);
#pragma unroll
    for (int off = 16; off; off >>= 1) part += __shfl_xor_sync(FULLM, part, off);
    __shared__ float warpsum[2];
    if ((c & 31) == 0) warpsum[c >> 5] = part;
    __syncthreads();
    if (c == 0) out[gidx] = warpsum[0] + warpsum[1] + __ldg(&fc2b[0]);
}

// ----------------------------- launch -----------------------------
extern "C" void kernel_launch(void* const* d_in, const int* in_sizes, int n_in,
                              void* d_out, int out_size) {
    const float* x      = (const float*)d_in[0];
    const void*  ei     = d_in[1];
    const void*  batch  = d_in[2];
    const float* W1     = (const float*)d_in[3];
    const float* a1_src = (const float*)d_in[4];
    const float* a1_dst = (const float*)d_in[5];
    const float* b1     = (const float*)d_in[6];
    const float* g1     = (const float*)d_in[7];
    const float* be1    = (const float*)d_in[8];
    const float* W2     = (const float*)d_in[9];
    const float* a2_src = (const float*)d_in[10];
    const float* a2_dst = (const float*)d_in[11];
    const float* b2     = (const float*)d_in[12];
    const float* g2     = (const float*)d_in[13];
    const float* be2    = (const float*)d_in[14];
    const float* W3     = (const float*)d_in[15];
    const float* a3_src = (const float*)d_in[16];
    const float* a3_dst = (const float*)d_in[17];
    const float* b3     = (const float*)d_in[18];
    const float* fc1_w  = (const float*)d_in[19];
    const float* fc1_b  = (const float*)d_in[20];
    const float* fc2_w  = (const float*)d_in[21];
    const float* fc2_b  = (const float*)d_in[22];
    float* out = (float*)d_out;

    const int EB = (E_TOT + 255) / 256;
    const int ATTN_B = (N_NODES + 7) / 8;
    const int GEMM_B = (N_NODES + 63) / 64;

    // graph structure (CSR by dst)
    detect_kernel<<<1, 256>>>(ei);
    zero_deg_kernel<<<(N_NODES + 255) / 256, 256>>>();
    convert_kernel<<<EB, 256>>>(ei, batch);
    scan_partial_kernel<<<SCAN_B, 512>>>();
    scan_mid_kernel<<<1, 128>>>();
    scan_final_kernel<<<SCAN_B, 512>>>();
    fill_kernel<<<EB, 256>>>();

    // ---- layer 1 ----
    gemm1_kernel<<<(N_NODES + 7) / 8, 256>>>(x, W1, a1_src, a1_dst);
    attn_kernel<4, 128, false><<<ATTN_B, 256>>>(b1);
    zero_bnsum_kernel<<<1, 256>>>();
    bnstats_kernel<<<(N_NODES + 127) / 128, 128>>>();

    // ---- layer 2 ----
    gemm_kernel<128><<<GEMM_B, 256>>>(W2, a2_src, a2_dst, g1, be1);
    attn_kernel<4, 128, false><<<ATTN_B, 256>>>(b2);
    zero_bnsum_kernel<<<1, 256>>>();
    bnstats_kernel<<<(N_NODES + 127) / 128, 128>>>();

    // ---- layer 3 ----
    gemm_kernel<64><<<GEMM_B, 256>>>(W3, a3_src, a3_dst, g2, be2);
    attn_kernel<1, 64, true><<<ATTN_B, 256>>>(b3);

    // ---- readout ----
    pool_kernel<<<N_GRAPHS, 128>>>();
    final_kernel<<<N_GRAPHS, 64>>>(fc1_w, fc1_b, fc2_w, fc2_b, out);
}

// round 6
// speedup vs baseline: 1.5381x; 1.2745x over previous
#include <cuda_runtime.h>
#include <cuda_fp16.h>
#include <cstdint>

#define N_NODES 100000
#define N_EDGES 1600000
#define E_TOT   (N_EDGES + N_NODES)   // self loops appended
#define N_GRAPHS 1024
#define EPS_BN 1e-5f
#define SCAN_B 98                      // ceil(N_NODES / 1024)
#define FULLM 0xffffffffu

// ----------------------------- scratch (device globals) -----------------------------
__device__ int    g_is64;
__device__ int    g_src[E_TOT];
__device__ int    g_dst[E_TOT];
__device__ int    g_batch[N_NODES];
__device__ int    g_deg[N_NODES];
__device__ int    g_off[N_NODES + 1];
__device__ int    g_cur[N_NODES];
__device__ int    g_csr[E_TOT];
__device__ int    g_bsum[SCAN_B];
__device__ __half g_hlinh[N_NODES * 128];  // post-GEMM features, fp16 (attn gather input)
__device__ float  g_feat[N_NODES * 128];   // attn output (raw, pre-BN) / GEMM input
__device__ float  g_als[N_NODES * 4];
__device__ float  g_ald[N_NODES * 4];
__device__ float  g_bnsum[256];            // [0:128) sum, [128:256) sumsq
__device__ float  g_pool[N_GRAPHS * 128];  // mean (0..63) || max (64..127)

// ----------------------------- utility -----------------------------
__device__ __forceinline__ float eluf(float v) { return v > 0.f ? v : expm1f(v); }
__device__ __forceinline__ float lrelu(float v) { return v > 0.f ? v : 0.2f * v; }

__device__ __forceinline__ uint32_t smem_u32(const void* p) {
    return (uint32_t)__cvta_generic_to_shared(p);
}
__device__ __forceinline__ void ldmatrix_x4(uint32_t* r, uint32_t addr) {
    asm volatile("ldmatrix.sync.aligned.m8n8.x4.shared.b16 {%0,%1,%2,%3}, [%4];"
                 : "=r"(r[0]), "=r"(r[1]), "=r"(r[2]), "=r"(r[3]) : "r"(addr));
}
__device__ __forceinline__ void ldmatrix_x2t(uint32_t& b0, uint32_t& b1, uint32_t addr) {
    asm volatile("ldmatrix.sync.aligned.m8n8.x2.trans.shared.b16 {%0,%1}, [%2];"
                 : "=r"(b0), "=r"(b1) : "r"(addr));
}
__device__ __forceinline__ void mma16816(float& d0, float& d1, float& d2, float& d3,
                                         const uint32_t* a, uint32_t b0, uint32_t b1) {
    asm volatile("mma.sync.aligned.m16n8k16.row.col.f32.f16.f16.f32 "
                 "{%0,%1,%2,%3}, {%4,%5,%6,%7}, {%8,%9}, {%0,%1,%2,%3};"
                 : "+f"(d0), "+f"(d1), "+f"(d2), "+f"(d3)
                 : "r"(a[0]), "r"(a[1]), "r"(a[2]), "r"(a[3]), "r"(b0), "r"(b1));
}

// ----------------------------- dtype detection -----------------------------
__global__ void detect_kernel(const void* ei) {
    __shared__ int any;
    if (threadIdx.x == 0) any = 0;
    __syncthreads();
    const int* p = (const int*)ei;
    int local = 0;
    for (int i = threadIdx.x; i < 2048; i += 256)
        if (p[2 * i + 1] != 0) local = 1;
    if (local) atomicOr(&any, 1);
    __syncthreads();
    if (threadIdx.x == 0) g_is64 = any ? 0 : 1;
}

__global__ void zero_deg_kernel() {
    int i = blockIdx.x * 256 + threadIdx.x;
    if (i < N_NODES) g_deg[i] = 0;
}

__global__ void convert_kernel(const void* ei, const void* batch) {
    int i = blockIdx.x * 256 + threadIdx.x;
    int is64 = g_is64;
    if (i < E_TOT) {
        int s, d;
        if (i < N_EDGES) {
            if (is64) {
                s = (int)((const long long*)ei)[i];
                d = (int)((const long long*)ei)[N_EDGES + i];
            } else {
                s = ((const int*)ei)[i];
                d = ((const int*)ei)[N_EDGES + i];
            }
        } else {
            s = d = i - N_EDGES;
        }
        g_src[i] = s;
        g_dst[i] = d;
        atomicAdd(&g_deg[d], 1);
    }
    if (i < N_NODES) {
        g_batch[i] = is64 ? (int)((const long long*)batch)[i] : ((const int*)batch)[i];
    }
}

// ----------------------------- hierarchical exclusive scan -----------------------------
__global__ void scan_partial_kernel() {
    __shared__ int sh[512];
    int t = threadIdx.x;
    int base = blockIdx.x * 1024;
    int i0 = base + t, i1 = base + 512 + t;
    int v = ((i0 < N_NODES) ? g_deg[i0] : 0) + ((i1 < N_NODES) ? g_deg[i1] : 0);
    sh[t] = v;
    __syncthreads();
    for (int o = 256; o; o >>= 1) {
        if (t < o) sh[t] += sh[t + o];
        __syncthreads();
    }
    if (t == 0) g_bsum[blockIdx.x] = sh[0];
}

__global__ void scan_mid_kernel() {
    __shared__ int sh[128];
    int t = threadIdx.x;
    int orig = (t < SCAN_B) ? g_bsum[t] : 0;
    sh[t] = orig;
    __syncthreads();
    for (int o = 1; o < 128; o <<= 1) {
        int v = (t >= o) ? sh[t - o] : 0;
        __syncthreads();
        sh[t] += v;
        __syncthreads();
    }
    if (t < SCAN_B) g_bsum[t] = sh[t] - orig;
    if (t == 0) g_off[N_NODES] = E_TOT;
}

__global__ void scan_final_kernel() {
    __shared__ int wsum[16];
    int t = threadIdx.x;
    int base = blockIdx.x * 1024;
    int i0 = base + 2 * t, i1 = i0 + 1;
    int d0 = (i0 < N_NODES) ? g_deg[i0] : 0;
    int d1 = (i1 < N_NODES) ? g_deg[i1] : 0;
    int tsum = d0 + d1;
    int lane = t & 31, wid = t >> 5;
    int v = tsum;
#pragma unroll
    for (int o = 1; o < 32; o <<= 1) {
        int u = __shfl_up_sync(FULLM, v, o);
        if (lane >= o) v += u;
    }
    if (lane == 31) wsum[wid] = v;
    __syncthreads();
    if (t < 16) {
        int w = wsum[t];
#pragma unroll
        for (int o = 1; o < 16; o <<= 1) {
            int u = __shfl_up_sync(0xffffu, w, o);
            if (t >= o) w += u;
        }
        wsum[t] = w;
    }
    __syncthreads();
    int excl = v - tsum + (wid ? wsum[wid - 1] : 0) + g_bsum[blockIdx.x];
    if (i0 < N_NODES) { g_off[i0] = excl;      g_cur[i0] = excl; }
    if (i1 < N_NODES) { g_off[i1] = excl + d0; g_cur[i1] = excl + d0; }
}

__global__ void fill_kernel() {
    int i = blockIdx.x * 256 + threadIdx.x;
    if (i < E_TOT) {
        int p = atomicAdd(&g_cur[g_dst[i]], 1);
        g_csr[p] = g_src[i];
    }
}

// ----------------------------- layer-1 GEMM (5 -> 128) + als epilogue -----------------------
__global__ void gemm1_kernel(const float* __restrict__ x, const float* __restrict__ W1,
                             const float* __restrict__ aS, const float* __restrict__ aD) {
    int node = blockIdx.x * 8 + (threadIdx.x >> 5);
    int lane = threadIdx.x & 31;
    if (node >= N_NODES) return;
    float acc[4] = {0.f, 0.f, 0.f, 0.f};
    const float* xr = x + node * 5;
#pragma unroll
    for (int k = 0; k < 5; k++) {
        float xv = __ldg(&xr[k]);
        float4 w = __ldg((const float4*)(W1 + k * 128 + lane * 4));
        acc[0] += xv * w.x; acc[1] += xv * w.y; acc[2] += xv * w.z; acc[3] += xv * w.w;
    }
    __half2 h0 = __floats2half2_rn(acc[0], acc[1]);
    __half2 h1 = __floats2half2_rn(acc[2], acc[3]);
    uint2 st;
    st.x = *(unsigned*)&h0; st.y = *(unsigned*)&h1;
    *(uint2*)(g_hlinh + node * 128 + lane * 4) = st;
    float pS = 0.f, pD = 0.f;
#pragma unroll
    for (int j = 0; j < 4; j++) {
        pS += acc[j] * __ldg(&aS[lane * 4 + j]);
        pD += acc[j] * __ldg(&aD[lane * 4 + j]);
    }
#pragma unroll
    for (int o = 1; o < 8; o <<= 1) {
        pS += __shfl_xor_sync(FULLM, pS, o);
        pD += __shfl_xor_sync(FULLM, pD, o);
    }
    if ((lane & 7) == 0) {
        int h = lane >> 3;
        g_als[node * 4 + h] = pS;
        g_ald[node * 4 + h] = pD;
    }
}

// ----------------------------- 128 -> OUTC GEMM via HMMA (tensor cores) ----------------------
// Block: 256 thr = 8 warps; tile 128 nodes x OUTC. Warp w owns rows [w*16, w*16+16).
// A = fp16(BN+ELU(g_feat)) in smem, B = fp16(W) in smem, fp32 accum.
// Epilogue: fp16 store to g_hlinh + als/ald dot products from fp32 accumulators.
template <int OUTC>
__global__ void __launch_bounds__(256) gemm_hmma(
        const float* __restrict__ W,
        const float* __restrict__ aS, const float* __restrict__ aD,
        const float* __restrict__ bnG, const float* __restrict__ bnBe) {
    constexpr int NT = OUTC / 8;              // n-tiles
    constexpr int H  = (OUTC == 128) ? 4 : 1; // heads
    constexpr int SA_STR = 136;               // halves per A row (16B-mult padding)
    constexpr int SB_STR = OUTC + 8;          // halves per B row

    extern __shared__ char smem[];
    __half* sA = (__half*)smem;                       // [128][SA_STR]
    __half* sB = sA + 128 * SA_STR;                   // [128][SB_STR]
    float* sScale = (float*)(sB + 128 * SB_STR);      // [128]
    float* sShift = sScale + 128;
    float* sAS = sShift + 128;                        // [OUTC] (128 slots)
    float* sAD = sAS + 128;

    int t = threadIdx.x;
    int warp = t >> 5, lane = t & 31;
    int nodeBase = blockIdx.x * 128;

    if (t < 128) {
        const float invN = 1.f / (float)N_NODES;
        float mu = g_bnsum[t] * invN;
        float var = g_bnsum[128 + t] * invN - mu * mu;
        float rs = rsqrtf(var + EPS_BN);
        float sc = rs * __ldg(&bnG[t]);
        sScale[t] = sc;
        sShift[t] = __ldg(&bnBe[t]) - mu * sc;
    }
    if (t < OUTC) {
        sAS[t] = __ldg(&aS[t]);
        sAD[t] = __ldg(&aD[t]);
    }
    __syncthreads();

    // A tile: 128x128 fp32 -> BN+ELU -> fp16
#pragma unroll
    for (int j = 0; j < 64; j++) {
        int idx = t + j * 256;
        int row = idx >> 7, col = idx & 127;
        int node = nodeBase + row;
        float v = 0.f;
        if (node < N_NODES)
            v = eluf(g_feat[node * 128 + col] * sScale[col] + sShift[col]);
        sA[row * SA_STR + col] = __float2half_rn(v);
    }
    // B tile: W [128][OUTC] fp32 -> fp16
#pragma unroll
    for (int j = 0; j < (128 * OUTC) / 256; j++) {
        int idx = t + j * 256;
        int k = idx / OUTC, n = idx % OUTC;
        sB[k * SB_STR + n] = __float2half_rn(__ldg(&W[idx]));
    }
    __syncthreads();

    // A fragments for this warp's 16 rows, all 8 k-steps
    uint32_t afr[8][4];
    {
        int arow = warp * 16 + (lane & 15);
        int acol = (lane >> 4) << 3;   // 0 or 8 halves
#pragma unroll
        for (int k8 = 0; k8 < 8; k8++) {
            uint32_t addr = smem_u32(&sA[arow * SA_STR + k8 * 16 + acol]);
            ldmatrix_x4(afr[k8], addr);
        }
    }

    float sS0[H], sS8[H], sD0[H], sD8[H];
#pragma unroll
    for (int h = 0; h < H; h++) { sS0[h] = 0.f; sS8[h] = 0.f; sD0[h] = 0.f; sD8[h] = 0.f; }

    int r = lane >> 2;
    int n0 = nodeBase + warp * 16 + r;
    int brow = lane & 15;

#pragma unroll
    for (int nt = 0; nt < NT; nt++) {
        float d0 = 0.f, d1 = 0.f, d2 = 0.f, d3 = 0.f;
#pragma unroll
        for (int k8 = 0; k8 < 8; k8++) {
            uint32_t b0, b1;
            uint32_t addr = smem_u32(&sB[(k8 * 16 + brow) * SB_STR + nt * 8]);
            ldmatrix_x2t(b0, b1, addr);
            mma16816(d0, d1, d2, d3, afr[k8], b0, b1);
        }
        int c = nt * 8 + 2 * (lane & 3);
        if (n0 < N_NODES)
            *(__half2*)(g_hlinh + (size_t)n0 * OUTC + c) = __floats2half2_rn(d0, d1);
        if (n0 + 8 < N_NODES)
            *(__half2*)(g_hlinh + (size_t)(n0 + 8) * OUTC + c) = __floats2half2_rn(d2, d3);
        constexpr int hh = 0;  // placeholder; real index below is compile-time per iteration
        (void)hh;
        int h = (OUTC == 128) ? (nt >> 2) : 0;
        float as0 = sAS[c], as1 = sAS[c + 1];
        float ad0 = sAD[c], ad1 = sAD[c + 1];
        sS0[h] += d0 * as0 + d1 * as1;
        sS8[h] += d2 * as0 + d3 * as1;
        sD0[h] += d0 * ad0 + d1 * ad1;
        sD8[h] += d2 * ad0 + d3 * ad1;
    }

    // reduce across the 4 threads of each row-quad
#pragma unroll
    for (int h = 0; h < H; h++) {
#pragma unroll
        for (int o = 1; o < 4; o <<= 1) {
            sS0[h] += __shfl_xor_sync(FULLM, sS0[h], o);
            sS8[h] += __shfl_xor_sync(FULLM, sS8[h], o);
            sD0[h] += __shfl_xor_sync(FULLM, sD0[h], o);
            sD8[h] += __shfl_xor_sync(FULLM, sD8[h], o);
        }
    }
    if ((lane & 3) == 0) {
        if (n0 < N_NODES) {
#pragma unroll
            for (int h = 0; h < H; h++) {
                g_als[n0 * H + h] = sS0[h];
                g_ald[n0 * H + h] = sD0[h];
            }
        }
        if (n0 + 8 < N_NODES) {
#pragma unroll
            for (int h = 0; h < H; h++) {
                g_als[(n0 + 8) * H + h] = sS8[h];
                g_ald[(n0 + 8) * H + h] = sD8[h];
            }
        }
    }
}

// ----------------------------- GAT aggregation: no-max softmax, width-8 ILP ------------------
template <int H, int HC, bool ELU_OUT>
__global__ void attn_kernel(const float* __restrict__ bias) {
    constexpr int K = HC / 32;
    constexpr int C = HC / H;
    constexpr int UW = 8;
    int node = (blockIdx.x * blockDim.x + threadIdx.x) >> 5;
    int lane = threadIdx.x & 31;
    if (node >= N_NODES) return;
    const int h0 = (lane * K) / C;

    float ad = g_ald[node * H + h0];
    float s = 0.f;
    float acc[K];
#pragma unroll
    for (int k = 0; k < K; k++) acc[k] = 0.f;

    int beg = g_off[node], end = g_off[node + 1];
    for (int base = beg; base < end; base += UW) {
        int srcu[UW];
        float alsu[UW];
        uint2 q4[UW];
        unsigned q2[UW];
#pragma unroll
        for (int u = 0; u < UW; u++)
            srcu[u] = (base + u < end) ? __ldg(&g_csr[base + u]) : 0;
#pragma unroll
        for (int u = 0; u < UW; u++)
            alsu[u] = (base + u < end) ? __ldg(&g_als[srcu[u] * H + h0]) : -1e30f;
#pragma unroll
        for (int u = 0; u < UW; u++) {
            if (K == 4)
                q4[u] = (base + u < end) ? *(const uint2*)(g_hlinh + (size_t)srcu[u] * HC + lane * 4)
                                         : make_uint2(0u, 0u);
            else
                q2[u] = (base + u < end) ? *(const unsigned*)(g_hlinh + (size_t)srcu[u] * HC + lane * 2)
                                         : 0u;
        }
#pragma unroll
        for (int u = 0; u < UW; u++) {
            float p = __expf(lrelu(alsu[u] + ad));
            s += p;
            if (K == 4) {
                float2 f0 = __half22float2(*(__half2*)&q4[u].x);
                float2 f1 = __half22float2(*(__half2*)&q4[u].y);
                acc[0] += p * f0.x; acc[1] += p * f0.y;
                acc[2] += p * f1.x; acc[3] += p * f1.y;
            } else {
                float2 f0 = __half22float2(*(__half2*)&q2[u]);
                acc[0] += p * f0.x; acc[1] += p * f0.y;
            }
        }
    }

    float inv = 1.f / (s + 1e-16f);
    if (K == 4) {
        float4 o;
        o.x = acc[0] * inv + __ldg(&bias[lane * 4 + 0]);
        o.y = acc[1] * inv + __ldg(&bias[lane * 4 + 1]);
        o.z = acc[2] * inv + __ldg(&bias[lane * 4 + 2]);
        o.w = acc[3] * inv + __ldg(&bias[lane * 4 + 3]);
        if (ELU_OUT) { o.x = eluf(o.x); o.y = eluf(o.y); o.z = eluf(o.z); o.w = eluf(o.w); }
        *(float4*)(g_feat + node * HC + lane * 4) = o;
    } else {
        float2 o;
        o.x = acc[0] * inv + __ldg(&bias[lane * 2 + 0]);
        o.y = acc[1] * inv + __ldg(&bias[lane * 2 + 1]);
        if (ELU_OUT) { o.x = eluf(o.x); o.y = eluf(o.y); }
        *(float2*)(g_feat + node * HC + lane * 2) = o;
    }
}

// ----------------------------- batch norm stats -----------------------------
__global__ void zero_bnsum_kernel() {
    if (threadIdx.x < 256) g_bnsum[threadIdx.x] = 0.f;
}

__global__ void bnstats_kernel() {
    int c = threadIdx.x;  // 128
    int n0 = blockIdx.x * 128;
    float s = 0.f, sq = 0.f;
    for (int r = 0; r < 128; r++) {
        int n = n0 + r;
        if (n < N_NODES) {
            float v = g_feat[n * 128 + c];
            s += v;
            sq += v * v;
        }
    }
    atomicAdd(&g_bnsum[c], s);
    atomicAdd(&g_bnsum[128 + c], sq);
}

// ----------------------------- pooling (batch sorted) -----------------------------
__device__ __forceinline__ int lower_bound_batch(int key) {
    int lo = 0, hi = N_NODES;
    while (lo < hi) {
        int mid = (lo + hi) >> 1;
        if (g_batch[mid] < key) lo = mid + 1;
        else hi = mid;
    }
    return lo;
}

__global__ void pool_kernel() {
    int gidx = blockIdx.x;
    __shared__ int se[2];
    if (threadIdx.x == 0) se[0] = lower_bound_batch(gidx);
    if (threadIdx.x == 1) se[1] = lower_bound_batch(gidx + 1);
    __syncthreads();
    int beg = se[0], end = se[1];
    int c = threadIdx.x & 63, sl = threadIdx.x >> 6;
    float sum = 0.f, mx = __int_as_float(0xff800000);
    for (int n = beg + sl; n < end; n += 2) {
        float v = g_feat[n * 64 + c];
        sum += v;
        mx = fmaxf(mx, v);
    }
    __shared__ float shs[128], shm[128];
    shs[threadIdx.x] = sum;
    shm[threadIdx.x] = mx;
    __syncthreads();
    if (sl == 0) {
        sum += shs[64 + c];
        mx = fmaxf(mx, shm[64 + c]);
        int cnt = end - beg;
        float mean = (cnt > 0) ? sum / (float)cnt : 0.f;
        float maxv = (cnt > 0) ? mx : 0.f;
        g_pool[gidx * 128 + c] = mean;
        g_pool[gidx * 128 + 64 + c] = maxv;
    }
}

// ----------------------------- classifier -----------------------------
__global__ void final_kernel(const float* __restrict__ fc1w, const float* __restrict__ fc1b,
                             const float* __restrict__ fc2w, const float* __restrict__ fc2b,
                             float* __restrict__ out) {
    int gidx = blockIdx.x;
    int c = threadIdx.x;  // 64
    __shared__ float hg[128];
    hg[c] = g_pool[gidx * 128 + c];
    hg[c + 64] = g_pool[gidx * 128 + 64 + c];
    __syncthreads();
    float acc = __ldg(&fc1b[c]);
#pragma unroll 8
    for (int k = 0; k < 128; k++) acc += hg[k] * __ldg(&fc1w[k * 64 + c]);
    float z = eluf(acc);
    float part = z * __ldg(&fc2w[c]);
#pragma unroll
    for (int off = 16; off; off >>= 1) part += __shfl_xor_sync(FULLM, part, off);
    __shared__ float warpsum[2];
    if ((c & 31) == 0) warpsum[c >> 5] = part;
    __syncthreads();
    if (c == 0) out[gidx] = warpsum[0] + warpsum[1] + __ldg(&fc2b[0]);
}

// ----------------------------- launch -----------------------------
extern "C" void kernel_launch(void* const* d_in, const int* in_sizes, int n_in,
                              void* d_out, int out_size) {
    const float* x      = (const float*)d_in[0];
    const void*  ei     = d_in[1];
    const void*  batch  = d_in[2];
    const float* W1     = (const float*)d_in[3];
    const float* a1_src = (const float*)d_in[4];
    const float* a1_dst = (const float*)d_in[5];
    const float* b1     = (const float*)d_in[6];
    const float* g1     = (const float*)d_in[7];
    const float* be1    = (const float*)d_in[8];
    const float* W2     = (const float*)d_in[9];
    const float* a2_src = (const float*)d_in[10];
    const float* a2_dst = (const float*)d_in[11];
    const float* b2     = (const float*)d_in[12];
    const float* g2     = (const float*)d_in[13];
    const float* be2    = (const float*)d_in[14];
    const float* W3     = (const float*)d_in[15];
    const float* a3_src = (const float*)d_in[16];
    const float* a3_dst = (const float*)d_in[17];
    const float* b3     = (const float*)d_in[18];
    const float* fc1_w  = (const float*)d_in[19];
    const float* fc1_b  = (const float*)d_in[20];
    const float* fc2_w  = (const float*)d_in[21];
    const float* fc2_b  = (const float*)d_in[22];
    float* out = (float*)d_out;

    const int EB = (E_TOT + 255) / 256;
    const int ATTN_B = (N_NODES + 7) / 8;
    const int HGB = (N_NODES + 127) / 128;   // HMMA gemm blocks

    // dynamic smem sizes for HMMA GEMMs
    const int SMEM2 = (128 * 136 + 128 * (128 + 8)) * 2 + 4 * 128 * 4;  // 71680
    const int SMEM3 = (128 * 136 + 128 * (64 + 8)) * 2 + 4 * 128 * 4;   // 55296
    static bool attr_set = false;
    if (!attr_set) {
        cudaFuncSetAttribute(gemm_hmma<128>, cudaFuncAttributeMaxDynamicSharedMemorySize, SMEM2);
        cudaFuncSetAttribute(gemm_hmma<64>,  cudaFuncAttributeMaxDynamicSharedMemorySize, SMEM3);
        attr_set = true;
    }

    // graph structure (CSR by dst)
    detect_kernel<<<1, 256>>>(ei);
    zero_deg_kernel<<<(N_NODES + 255) / 256, 256>>>();
    convert_kernel<<<EB, 256>>>(ei, batch);
    scan_partial_kernel<<<SCAN_B, 512>>>();
    scan_mid_kernel<<<1, 128>>>();
    scan_final_kernel<<<SCAN_B, 512>>>();
    fill_kernel<<<EB, 256>>>();

    // ---- layer 1 ----
    gemm1_kernel<<<(N_NODES + 7) / 8, 256>>>(x, W1, a1_src, a1_dst);
    attn_kernel<4, 128, false><<<ATTN_B, 256>>>(b1);
    zero_bnsum_kernel<<<1, 256>>>();
    bnstats_kernel<<<HGB, 128>>>();

    // ---- layer 2 (tensor-core GEMM, BN fused in, als fused out) ----
    gemm_hmma<128><<<HGB, 256, SMEM2>>>(W2, a2_src, a2_dst, g1, be1);
    attn_kernel<4, 128, false><<<ATTN_B, 256>>>(b2);
    zero_bnsum_kernel<<<1, 256>>>();
    bnstats_kernel<<<HGB, 128>>>();

    // ---- layer 3 ----
    gemm_hmma<64><<<HGB, 256, SMEM3>>>(W3, a3_src, a3_dst, g2, be2);
    attn_kernel<1, 64, true><<<ATTN_B, 256>>>(b3);

    // ---- readout ----
    pool_kernel<<<N_GRAPHS, 128>>>();
    final_kernel<<<N_GRAPHS, 64>>>(fc1_w, fc1_b, fc2_w, fc2_b, out);
}